// round 11
// baseline (speedup 1.0000x reference)
#include <cuda_runtime.h>

#define Nn 10000
#define Ee 640000
#define Hh 128
#define Bb 64

#define EDGE_TPB   256
#define EDGE_BATCH 4
#define NB_EDGE    (Ee / (EDGE_TPB * EDGE_BATCH))   // 625 (exact: 625*256*4 = 640000)

#define SMEM_W_FLOATS (Hh * Hh)                      // 16384 floats = 64KB
#define LAYER_SMEM ((SMEM_W_FLOATS + 8 * Hh) * 4)    // 64KB W + 4KB agg = 69632B

// ---------------- scratch (device globals) ----------------------------------
__device__ int   g_cnt[Nn];            // zeroed by loader (call 1) then by tail
__device__ int   g_off[Nn + 1];
__device__ int   g_cur[Nn];
__device__ int2  g_edge[Ee];           // {src*Hh, norm bits} per CSR slot
__device__ float g_dinv[Nn];
__device__ float g_hA[Nn * Hh];        // ping
__device__ float g_hB[Nn * Hh];        // pong
__device__ float g_pool[Bb * Hh + Bb]; // zeroed by loader then by tail

// ---------------- degree count (4 edges/thread, exact cover) -----------------
__global__ void cnt_kernel(const int* __restrict__ dst) {
    int e0 = blockIdx.x * EDGE_TPB + threadIdx.x;
    int d[EDGE_BATCH];
#pragma unroll
    for (int j = 0; j < EDGE_BATCH; j++) d[j] = dst[e0 + j * (NB_EDGE * EDGE_TPB)];
#pragma unroll
    for (int j = 0; j < EDGE_BATCH; j++) atomicAdd(&g_cnt[d[j]], 1);
}

// ---------------- scan: 1 block, 1024 threads, 10 elems/thread ---------------
__global__ void scan_kernel() {
    __shared__ int wsum[32];
    int t = threadIdx.x, lane = t & 31, w = t >> 5;
    int base = t * 10;
    int v[10];
    int s = 0;
#pragma unroll
    for (int j = 0; j < 10; j++) {
        int i = base + j;
        v[j] = (i < Nn) ? g_cnt[i] : 0;
        s += v[j];
    }
    // block exclusive scan of per-thread sums
    int incl = s;
#pragma unroll
    for (int o = 1; o < 32; o <<= 1) {
        int x = __shfl_up_sync(0xffffffffu, incl, o);
        if (lane >= o) incl += x;
    }
    if (lane == 31) wsum[w] = incl;
    __syncthreads();
    if (w == 0) {
        int x = wsum[lane];
        int s2 = x;
#pragma unroll
        for (int o = 1; o < 32; o <<= 1) {
            int y = __shfl_up_sync(0xffffffffu, s2, o);
            if (lane >= o) s2 += y;
        }
        wsum[lane] = s2 - x;   // exclusive warp offsets
    }
    __syncthreads();
    int run = wsum[w] + incl - s;   // exclusive prefix for this thread
#pragma unroll
    for (int j = 0; j < 10; j++) {
        int i = base + j;
        if (i < Nn) {
            g_off[i] = run;
            g_cur[i] = run;
            g_dinv[i] = rsqrtf((float)v[j] + 1.0f);  // +1 self loop
            run += v[j];
        }
    }
    if (t == 1000) g_off[Nn] = run;   // base==Nn exactly: run == total
}

// ---------------- CSR fill (4 edges/thread) ----------------------------------
__global__ void fill_kernel(const int* __restrict__ src, const int* __restrict__ dst) {
    int e0 = blockIdx.x * EDGE_TPB + threadIdx.x;
    int s[EDGE_BATCH], d[EDGE_BATCH];
#pragma unroll
    for (int j = 0; j < EDGE_BATCH; j++) {
        int e = e0 + j * (NB_EDGE * EDGE_TPB);
        s[j] = src[e];
        d[j] = dst[e];
    }
    float nm[EDGE_BATCH];
#pragma unroll
    for (int j = 0; j < EDGE_BATCH; j++) nm[j] = g_dinv[s[j]] * g_dinv[d[j]];
    int pos[EDGE_BATCH];
#pragma unroll
    for (int j = 0; j < EDGE_BATCH; j++) pos[j] = atomicAdd(&g_cur[d[j]], 1);
#pragma unroll
    for (int j = 0; j < EDGE_BATCH; j++)
        g_edge[pos[j]] = make_int2(s[j] * Hh, __float_as_int(nm[j]));
}

// ---------------- fused layer: agg = A_norm · in ; out = agg @ W + b ---------
// 256 threads = 8 warps = 8 nodes/block. W in dynamic smem (64KB).
// mode 1: relu -> outp ; mode 0: linear -> outp ; mode 2: linear -> pool atomics
__global__ void layer_kernel(const float* __restrict__ in,
                             const float* __restrict__ W,
                             const float* __restrict__ bias,
                             float* __restrict__ outp,
                             int mode,
                             const int* __restrict__ batch) {
    extern __shared__ float sm[];
    float* Ws = sm;                        // [128][128]
    float* aggs = sm + SMEM_W_FLOATS;      // [8][128]

    int tid = threadIdx.x;

    // ---- stage W into smem (coalesced float4; W is L2-hot after block 0) ----
    {
        const float4* Wv = (const float4*)W;
        float4* Sv = (float4*)Ws;
#pragma unroll
        for (int it = 0; it < (SMEM_W_FLOATS / 4) / 256; it++)   // 16 iters
            Sv[it * 256 + tid] = Wv[it * 256 + tid];
    }

    int w = tid >> 5, lane = tid & 31;
    int i = blockIdx.x * 8 + w;
    int lo4 = lane * 4;

    // ---- gather phase: agg = sum_e norm * in[src] + dinv^2 * in[i] ----------
    float4 acc = make_float4(0.f, 0.f, 0.f, 0.f);
    if (i < Nn) {
        int beg = g_off[i];
        int end = g_off[i + 1];
        int p = beg;
        for (; p + 3 < end; p += 4) {
            int2 e0 = g_edge[p + 0], e1 = g_edge[p + 1], e2 = g_edge[p + 2], e3 = g_edge[p + 3];
            float n0 = __int_as_float(e0.y), n1 = __int_as_float(e1.y);
            float n2 = __int_as_float(e2.y), n3 = __int_as_float(e3.y);
            float4 v0 = *(const float4*)&in[e0.x + lo4];
            float4 v1 = *(const float4*)&in[e1.x + lo4];
            float4 v2 = *(const float4*)&in[e2.x + lo4];
            float4 v3 = *(const float4*)&in[e3.x + lo4];
            acc.x += n0 * v0.x + n1 * v1.x + n2 * v2.x + n3 * v3.x;
            acc.y += n0 * v0.y + n1 * v1.y + n2 * v2.y + n3 * v3.y;
            acc.z += n0 * v0.z + n1 * v1.z + n2 * v2.z + n3 * v3.z;
            acc.w += n0 * v0.w + n1 * v1.w + n2 * v2.w + n3 * v3.w;
        }
        for (; p < end; p++) {
            int2 e = g_edge[p];
            float nm = __int_as_float(e.y);
            float4 v = *(const float4*)&in[e.x + lo4];
            acc.x += nm * v.x;
            acc.y += nm * v.y;
            acc.z += nm * v.z;
            acc.w += nm * v.w;
        }
        // self-loop on raw input
        float di = g_dinv[i];
        float d2 = di * di;
        float4 tv = *(const float4*)&in[i * Hh + lo4];
        acc.x += d2 * tv.x;
        acc.y += d2 * tv.y;
        acc.z += d2 * tv.z;
        acc.w += d2 * tv.w;
    }
    *(float4*)&aggs[w * Hh + lo4] = acc;
    __syncthreads();   // W staged + own agg visible

    if (i >= Nn) return;

    // ---- GEMV phase: out[i][lo4..lo4+3] = agg_row @ W + b -------------------
    float4 o = *(const float4*)&bias[lo4];
    const float* arow = &aggs[w * Hh];
#pragma unroll 8
    for (int k = 0; k < Hh; k += 4) {
        float4 a4 = *(const float4*)&arow[k];                      // broadcast
        float4 w0 = *(const float4*)&Ws[(k + 0) * Hh + lo4];
        float4 w1 = *(const float4*)&Ws[(k + 1) * Hh + lo4];
        float4 w2 = *(const float4*)&Ws[(k + 2) * Hh + lo4];
        float4 w3 = *(const float4*)&Ws[(k + 3) * Hh + lo4];
        o.x += a4.x * w0.x + a4.y * w1.x + a4.z * w2.x + a4.w * w3.x;
        o.y += a4.x * w0.y + a4.y * w1.y + a4.z * w2.y + a4.w * w3.y;
        o.z += a4.x * w0.z + a4.y * w1.z + a4.z * w2.z + a4.w * w3.z;
        o.w += a4.x * w0.w + a4.y * w1.w + a4.z * w2.w + a4.w * w3.w;
    }

    if (mode == 1) {
        o.x = fmaxf(o.x, 0.f);
        o.y = fmaxf(o.y, 0.f);
        o.z = fmaxf(o.z, 0.f);
        o.w = fmaxf(o.w, 0.f);
        *(float4*)&outp[i * Hh + lo4] = o;
    } else if (mode == 0) {
        *(float4*)&outp[i * Hh + lo4] = o;
    } else {
        int bg = batch[i];
        float* pp = &g_pool[bg * Hh + lo4];
        atomicAdd(pp + 0, o.x);
        atomicAdd(pp + 1, o.y);
        atomicAdd(pp + 2, o.z);
        atomicAdd(pp + 3, o.w);
        if (lane == 0) atomicAdd(&g_pool[Bb * Hh + bg], 1.0f);
    }
}

// ---------------- head + tail-zero for next replay ---------------------------
__global__ void head_tail_kernel(const float* __restrict__ Wp, const float* __restrict__ bp,
                                 float* __restrict__ out) {
    if (blockIdx.x < 8) {
        int t = blockIdx.x * blockDim.x + threadIdx.x;
        int g = t >> 5;
        int lane = t & 31;
        if (g >= Bb) return;
        float c = g_pool[Bb * Hh + g];
        float inv = 1.0f / fmaxf(c, 1.0f);
        float4 v = ((const float4*)g_pool)[g * 32 + lane];
        float4 w = ((const float4*)Wp)[lane];
        float s = v.x * w.x + v.y * w.y + v.z * w.z + v.w * w.w;
#pragma unroll
        for (int o = 16; o; o >>= 1) s += __shfl_xor_sync(0xffffffffu, s, o);
        if (lane == 0) {
            out[g] = s * inv + bp[0];
            g_pool[Bb * Hh + g] = 0.0f;           // re-zero count for next replay
        }
        ((float4*)g_pool)[g * 32 + lane] = make_float4(0.f, 0.f, 0.f, 0.f);
    } else {
        int i = (blockIdx.x - 8) * blockDim.x + threadIdx.x;
        if (i < Nn) g_cnt[i] = 0;                 // re-zero degrees for next replay
    }
}

// ---------------- launch ----------------------------------------------------
extern "C" void kernel_launch(void* const* d_in, const int* in_sizes, int n_in,
                              void* d_out, int out_size) {
    const float* x     = (const float*)d_in[0];
    const int*   ei    = (const int*)d_in[1];
    const int*   batch = (const int*)d_in[2];
    const float* W1    = (const float*)d_in[3];
    const float* b1    = (const float*)d_in[4];
    const float* W2    = (const float*)d_in[5];
    const float* b2    = (const float*)d_in[6];
    const float* W3    = (const float*)d_in[7];
    const float* b3    = (const float*)d_in[8];
    const float* Wp    = (const float*)d_in[9];
    const float* bp    = (const float*)d_in[10];
    float* out = (float*)d_out;

    const int* src = ei;        // edge_index[0]
    const int* dst = ei + Ee;   // edge_index[1]

    float* hA = nullptr;
    float* hB = nullptr;
    cudaGetSymbolAddress((void**)&hA, g_hA);
    cudaGetSymbolAddress((void**)&hB, g_hB);

    cudaFuncSetAttribute(layer_kernel, cudaFuncAttributeMaxDynamicSharedMemorySize,
                         LAYER_SMEM);

    const int T = 256;
    int nb_layer = (Nn + 7) / 8;     // 1250

    // ---- CSR build + normalization (once, shared by all 3 layers) ----
    cnt_kernel<<<NB_EDGE, T>>>(dst);
    scan_kernel<<<1, 1024>>>();
    fill_kernel<<<NB_EDGE, T>>>(src, dst);

    // ---- 3 fused layers: gather raw -> GEMV (A·(hW) == (A·h)·W) ----
    layer_kernel<<<nb_layer, T, LAYER_SMEM>>>(x,  W1, b1, hA, 1, batch);
    layer_kernel<<<nb_layer, T, LAYER_SMEM>>>(hA, W2, b2, hB, 1, batch);
    layer_kernel<<<nb_layer, T, LAYER_SMEM>>>(hB, W3, b3, hA, 2, batch);

    // ---- head + tail-zero (pool & cnt reset for next replay) ----
    head_tail_kernel<<<8 + (Nn + T - 1) / T, T>>>(Wp, bp, out);
}

// round 12
// speedup vs baseline: 1.6513x; 1.6513x over previous
#include <cuda_runtime.h>
#include <cuda_fp16.h>

#define Nn 10000
#define Ee 640000
#define Hh 128
#define Bb 64

#define NB_GEMM   ((Nn + 63) / 64)          // 157
#define NB_GEMM_A 79                        // rows [0, 5056)
#define NB_GEMM_B (NB_GEMM - NB_GEMM_A)     // 78: rows [5056, 10000)
#define EDGE_TPB  256
#define EDGE_BATCH 4
#define NB_EDGE   (Ee / (EDGE_TPB * EDGE_BATCH))   // 625 (exact)

// ---------------- scratch (device globals) ----------------------------------
__device__ int    g_cnt[Nn];          // zeroed by loader (call 1) then by tail
__device__ int    g_off[Nn + 1];
__device__ int    g_cur[Nn];
__device__ int2   g_edge[Ee];         // {src*Hh, norm bits} per CSR slot
__device__ float  g_dinv[Nn];
__device__ __half g_tmp[Nn * Hh];     // h @ W (per layer), fp16 messages
__device__ float  g_h[Nn * Hh];       // layer output (fp32)
__device__ float  g_pool[Bb * Hh + Bb];  // zeroed by loader then by tail

// ---------------- GEMM body: fp32 compute, fp16 store ------------------------
// 256 threads, tile 64 rows x 128 cols, BK=32; thread tile 8 rows x 4 cols
__device__ __forceinline__ void gemm_body(const float* __restrict__ A,
                                          const float* __restrict__ W,
                                          int rowBase) {
    __shared__ float As[64][32];
    __shared__ float Ws[32][128];

    int tid = threadIdx.x;
    int tx = tid & 31;    // cols tx*4
    int ty = tid >> 5;    // rows ty*8

    float acc[8][4];
#pragma unroll
    for (int r = 0; r < 8; r++)
#pragma unroll
        for (int c = 0; c < 4; c++) acc[r][c] = 0.0f;

    for (int kk = 0; kk < Hh; kk += 32) {
#pragma unroll
        for (int i = 0; i < 2; i++) {
            int lin = tid * 2 + i;          // 0..511 float4 slots (64x8)
            int r = lin >> 3, c4 = lin & 7;
            int row = rowBase + r;
            float4 v = make_float4(0.f, 0.f, 0.f, 0.f);
            if (row < Nn) v = *(const float4*)&A[row * Hh + kk + c4 * 4];
            *(float4*)&As[r][c4 * 4] = v;
        }
#pragma unroll
        for (int i = 0; i < 4; i++) {
            int lin = i * 256 + tid;        // 0..1023 float4 slots (32x32)
            int r = lin >> 5, c4 = lin & 31;
            *(float4*)&Ws[r][c4 * 4] = *(const float4*)&W[(kk + r) * Hh + c4 * 4];
        }
        __syncthreads();
#pragma unroll
        for (int k = 0; k < 32; k++) {
            float4 b = *(float4*)&Ws[k][tx * 4];
#pragma unroll
            for (int r = 0; r < 8; r++) {
                float a = As[ty * 8 + r][k];
                acc[r][0] += a * b.x;
                acc[r][1] += a * b.y;
                acc[r][2] += a * b.z;
                acc[r][3] += a * b.w;
            }
        }
        __syncthreads();
    }
#pragma unroll
    for (int r = 0; r < 8; r++) {
        int row = rowBase + ty * 8 + r;
        if (row < Nn) {
            __half2 h01 = __floats2half2_rn(acc[r][0], acc[r][1]);
            __half2 h23 = __floats2half2_rn(acc[r][2], acc[r][3]);
            uint2 u;
            u.x = *(unsigned int*)&h01;
            u.y = *(unsigned int*)&h23;
            *(uint2*)&g_tmp[row * Hh + tx * 4] = u;   // 8B aligned
        }
    }
}

__global__ void gemm_kernel(const float* __restrict__ A, const float* __restrict__ W) {
    gemm_body(A, W, blockIdx.x * 64);
}

// ---------------- phase 1: degree count fused with GEMM1 (rows 0..5055) ------
__global__ void cnt_gemm1a_kernel(const int* __restrict__ dst,
                                  const float* __restrict__ A,
                                  const float* __restrict__ W) {
    if (blockIdx.x < NB_GEMM_A) {
        gemm_body(A, W, blockIdx.x * 64);
    } else {
        int e0 = (blockIdx.x - NB_GEMM_A) * EDGE_TPB + threadIdx.x;
        int d[EDGE_BATCH];
#pragma unroll
        for (int j = 0; j < EDGE_BATCH; j++) {
            int e = e0 + j * (NB_EDGE * EDGE_TPB);
            d[j] = (e < Ee) ? dst[e] : -1;
        }
#pragma unroll
        for (int j = 0; j < EDGE_BATCH; j++)
            if (d[j] >= 0) atomicAdd(&g_cnt[d[j]], 1);
    }
}

// ---------------- scan: exclusive prefix of g_cnt; emits dinv & cur ----------
__global__ void scan_kernel() {
    __shared__ int wsum[32];
    __shared__ int carry_s;
    int t = threadIdx.x, lane = t & 31, w = t >> 5;
    if (t == 0) carry_s = 0;
    __syncthreads();
    for (int base = 0; base < Nn; base += 1024) {
        int i = base + t;
        int v = (i < Nn) ? g_cnt[i] : 0;
        int incl = v;
#pragma unroll
        for (int o = 1; o < 32; o <<= 1) {
            int x = __shfl_up_sync(0xffffffffu, incl, o);
            if (lane >= o) incl += x;
        }
        if (lane == 31) wsum[w] = incl;
        __syncthreads();
        if (w == 0) {
            int x = wsum[lane];
            int s2 = x;
#pragma unroll
            for (int o = 1; o < 32; o <<= 1) {
                int y = __shfl_up_sync(0xffffffffu, s2, o);
                if (lane >= o) s2 += y;
            }
            wsum[lane] = s2 - x;   // exclusive warp offsets
        }
        __syncthreads();
        int carry = carry_s;
        if (i < Nn) {
            int off = carry + wsum[w] + incl - v;
            g_off[i] = off;
            g_cur[i] = off;
            g_dinv[i] = rsqrtf((float)v + 1.0f);  // +1 self loop
        }
        __syncthreads();
        if (t == 1023) carry_s = carry + wsum[31] + incl;
        __syncthreads();
    }
    if (threadIdx.x == 0) g_off[Nn] = carry_s;
}

// ---------------- phase 2: CSR fill fused with GEMM1 (rows 5056..9999) -------
__global__ void fill_gemm1b_kernel(const int* __restrict__ src, const int* __restrict__ dst,
                                   const float* __restrict__ A, const float* __restrict__ W) {
    if (blockIdx.x < NB_GEMM_B) {
        gemm_body(A, W, (blockIdx.x + NB_GEMM_A) * 64);
    } else {
        int e0 = (blockIdx.x - NB_GEMM_B) * EDGE_TPB + threadIdx.x;
        int s[EDGE_BATCH], d[EDGE_BATCH];
        float nm[EDGE_BATCH];
#pragma unroll
        for (int j = 0; j < EDGE_BATCH; j++) {
            int e = e0 + j * (NB_EDGE * EDGE_TPB);
            if (e < Ee) {
                s[j] = src[e];
                d[j] = dst[e];
            } else {
                s[j] = -1;
                d[j] = 0;
            }
        }
#pragma unroll
        for (int j = 0; j < EDGE_BATCH; j++)
            if (s[j] >= 0) nm[j] = g_dinv[s[j]] * g_dinv[d[j]];
        int pos[EDGE_BATCH];
#pragma unroll
        for (int j = 0; j < EDGE_BATCH; j++)
            pos[j] = (s[j] >= 0) ? atomicAdd(&g_cur[d[j]], 1) : -1;
#pragma unroll
        for (int j = 0; j < EDGE_BATCH; j++)
            if (pos[j] >= 0)
                g_edge[pos[j]] = make_int2(s[j] * Hh, __float_as_int(nm[j]));
    }
}

// ---------------- fused gather + epilogue (fp16 messages) --------------------
// one warp per destination node; register float4 accumulator; no atomics.
// mode: 1 = relu -> g_h, 0 = linear -> g_h, 2 = linear -> pool atomics
__device__ __forceinline__ float4 ld_msg(int off) {
    uint2 u = *(const uint2*)&g_tmp[off];
    __half2 h0 = *(__half2*)&u.x;
    __half2 h1 = *(__half2*)&u.y;
    float2 f0 = __half22float2(h0);
    float2 f1 = __half22float2(h1);
    return make_float4(f0.x, f0.y, f1.x, f1.y);
}

__global__ void gather_kernel(const float* __restrict__ bias, int mode,
                              const int* __restrict__ batch) {
    int t = blockIdx.x * blockDim.x + threadIdx.x;
    int i = t >> 5;          // node
    int lane = t & 31;
    if (i >= Nn) return;

    int beg = g_off[i];
    int end = g_off[i + 1];
    int lo4 = lane * 4;

    float4 acc = make_float4(0.f, 0.f, 0.f, 0.f);
    int p = beg;
    for (; p + 3 < end; p += 4) {
        int2 e0 = g_edge[p + 0], e1 = g_edge[p + 1], e2 = g_edge[p + 2], e3 = g_edge[p + 3];
        float n0 = __int_as_float(e0.y), n1 = __int_as_float(e1.y);
        float n2 = __int_as_float(e2.y), n3 = __int_as_float(e3.y);
        float4 v0 = ld_msg(e0.x + lo4);
        float4 v1 = ld_msg(e1.x + lo4);
        float4 v2 = ld_msg(e2.x + lo4);
        float4 v3 = ld_msg(e3.x + lo4);
        acc.x += n0 * v0.x + n1 * v1.x + n2 * v2.x + n3 * v3.x;
        acc.y += n0 * v0.y + n1 * v1.y + n2 * v2.y + n3 * v3.y;
        acc.z += n0 * v0.z + n1 * v1.z + n2 * v2.z + n3 * v3.z;
        acc.w += n0 * v0.w + n1 * v1.w + n2 * v2.w + n3 * v3.w;
    }
    for (; p < end; p++) {
        int2 e = g_edge[p];
        float nm = __int_as_float(e.y);
        float4 v = ld_msg(e.x + lo4);
        acc.x += nm * v.x;
        acc.y += nm * v.y;
        acc.z += nm * v.z;
        acc.w += nm * v.w;
    }

    // self-loop + bias
    float di = g_dinv[i];
    float d2 = di * di;
    float4 tv = ld_msg(i * Hh + lo4);
    float4 b = ((const float4*)bias)[lane];
    float4 r;
    r.x = acc.x + d2 * tv.x + b.x;
    r.y = acc.y + d2 * tv.y + b.y;
    r.z = acc.z + d2 * tv.z + b.z;
    r.w = acc.w + d2 * tv.w + b.w;

    if (mode == 1) {
        r.x = fmaxf(r.x, 0.f);
        r.y = fmaxf(r.y, 0.f);
        r.z = fmaxf(r.z, 0.f);
        r.w = fmaxf(r.w, 0.f);
        ((float4*)g_h)[i * 32 + lane] = r;
    } else if (mode == 0) {
        ((float4*)g_h)[i * 32 + lane] = r;
    } else {
        int bg = batch[i];
        float* pp = &g_pool[bg * Hh + lo4];
        atomicAdd(pp + 0, r.x);
        atomicAdd(pp + 1, r.y);
        atomicAdd(pp + 2, r.z);
        atomicAdd(pp + 3, r.w);
        if (lane == 0) atomicAdd(&g_pool[Bb * Hh + bg], 1.0f);
    }
}

// ---------------- head + tail-zero for next replay ---------------------------
__global__ void head_tail_kernel(const float* __restrict__ Wp, const float* __restrict__ bp,
                                 float* __restrict__ out) {
    if (blockIdx.x < 8) {
        int t = blockIdx.x * blockDim.x + threadIdx.x;
        int g = t >> 5;
        int lane = t & 31;
        if (g >= Bb) return;
        float c = g_pool[Bb * Hh + g];
        float inv = 1.0f / fmaxf(c, 1.0f);
        float4 v = ((const float4*)g_pool)[g * 32 + lane];
        float4 w = ((const float4*)Wp)[lane];
        float s = v.x * w.x + v.y * w.y + v.z * w.z + v.w * w.w;
#pragma unroll
        for (int o = 16; o; o >>= 1) s += __shfl_xor_sync(0xffffffffu, s, o);
        if (lane == 0) {
            out[g] = s * inv + bp[0];
            g_pool[Bb * Hh + g] = 0.0f;           // re-zero count for next replay
        }
        ((float4*)g_pool)[g * 32 + lane] = make_float4(0.f, 0.f, 0.f, 0.f);
    } else {
        int i = (blockIdx.x - 8) * blockDim.x + threadIdx.x;
        if (i < Nn) g_cnt[i] = 0;                 // re-zero degrees for next replay
    }
}

// ---------------- launch ----------------------------------------------------
extern "C" void kernel_launch(void* const* d_in, const int* in_sizes, int n_in,
                              void* d_out, int out_size) {
    const float* x     = (const float*)d_in[0];
    const int*   ei    = (const int*)d_in[1];
    const int*   batch = (const int*)d_in[2];
    const float* W1    = (const float*)d_in[3];
    const float* b1    = (const float*)d_in[4];
    const float* W2    = (const float*)d_in[5];
    const float* b2    = (const float*)d_in[6];
    const float* W3    = (const float*)d_in[7];
    const float* b3    = (const float*)d_in[8];
    const float* Wp    = (const float*)d_in[9];
    const float* bp    = (const float*)d_in[10];
    float* out = (float*)d_out;

    const int* src = ei;        // edge_index[0]
    const int* dst = ei + Ee;   // edge_index[1]

    float* hbuf = nullptr;
    cudaGetSymbolAddress((void**)&hbuf, g_h);

    const int T = 256;
    int nb_Nw = (Nn * 32 + T - 1) / T;        // 1250

    // phase 1: degree count || GEMM1 (first half of rows)
    cnt_gemm1a_kernel<<<NB_GEMM_A + NB_EDGE, T>>>(dst, x, W1);
    // offsets + dinv
    scan_kernel<<<1, 1024>>>();
    // phase 2: CSR fill || GEMM1 (second half of rows)
    fill_gemm1b_kernel<<<NB_GEMM_B + NB_EDGE, T>>>(src, dst, x, W1);

    // layer 1 aggregate
    gather_kernel<<<nb_Nw, T>>>(b1, 1, batch);

    // layer 2
    gemm_kernel<<<NB_GEMM, T>>>(hbuf, W2);
    gather_kernel<<<nb_Nw, T>>>(b2, 1, batch);

    // layer 3 (fused with pooling)
    gemm_kernel<<<NB_GEMM, T>>>(hbuf, W3);
    gather_kernel<<<nb_Nw, T>>>(b3, 2, batch);

    // head + tail-zero (pool & cnt reset for next replay)
    head_tail_kernel<<<8 + (Nn + T - 1) / T, T>>>(Wp, bp, out);
}

// round 15
// speedup vs baseline: 1.6775x; 1.0159x over previous
#include <cuda_runtime.h>
#include <cuda_fp16.h>

#define Nn 10000
#define Ee 640000
#define Hh 128
#define Bb 64

#define GEMM_ROWS 32
#define NB_GEMM   ((Nn + GEMM_ROWS - 1) / GEMM_ROWS)   // 313
#define NB_GEMM_A 157                                   // rows [0, 5024)
#define NB_GEMM_B (NB_GEMM - NB_GEMM_A)                 // 156: rows [5024, 10016)
#define EDGE_TPB  256
#define EDGE_BATCH 4
#define NB_EDGE   (Ee / (EDGE_TPB * EDGE_BATCH))        // 625 (exact)

// ---------------- scratch (device globals) ----------------------------------
__device__ int    g_cnt[Nn];          // zeroed by loader (call 1) then by tail
__device__ int    g_off[Nn + 1];
__device__ int    g_cur[Nn];
__device__ int2   g_edge[Ee];         // {src*Hh, norm bits} per CSR slot
__device__ float  g_dinv[Nn];
__device__ __half g_tmp[Nn * Hh];     // h @ W (per layer), fp16 messages
__device__ float  g_h[Nn * Hh];       // layer output (fp32)
__device__ float  g_pool[Bb * Hh + Bb];  // zeroed by loader then by tail

// ---------------- GEMM body: 32x128 tile, fp32 compute, fp16 store ----------
// 256 threads; thread tile 4 rows x 4 cols; BK=32
__device__ __forceinline__ void gemm_body(const float* __restrict__ A,
                                          const float* __restrict__ W,
                                          int rowBase) {
    __shared__ float As[32][32];
    __shared__ float Ws[32][128];

    int tid = threadIdx.x;
    int tx = tid & 31;    // cols tx*4
    int ty = tid >> 5;    // rows ty*4

    float acc[4][4];
#pragma unroll
    for (int r = 0; r < 4; r++)
#pragma unroll
        for (int c = 0; c < 4; c++) acc[r][c] = 0.0f;

    for (int kk = 0; kk < Hh; kk += 32) {
        // A tile: 32 rows x 32 k = 256 float4, 1 per thread
        {
            int r = tid >> 3, c4 = tid & 7;
            int row = rowBase + r;
            float4 v = make_float4(0.f, 0.f, 0.f, 0.f);
            if (row < Nn) v = *(const float4*)&A[row * Hh + kk + c4 * 4];
            *(float4*)&As[r][c4 * 4] = v;
        }
        // W tile: 32 k x 128 cols = 1024 float4, 4 per thread
#pragma unroll
        for (int i = 0; i < 4; i++) {
            int lin = i * 256 + tid;
            int r = lin >> 5, c4 = lin & 31;
            *(float4*)&Ws[r][c4 * 4] = *(const float4*)&W[(kk + r) * Hh + c4 * 4];
        }
        __syncthreads();
#pragma unroll
        for (int k = 0; k < 32; k++) {
            float4 b = *(float4*)&Ws[k][tx * 4];
#pragma unroll
            for (int r = 0; r < 4; r++) {
                float a = As[ty * 4 + r][k];
                acc[r][0] += a * b.x;
                acc[r][1] += a * b.y;
                acc[r][2] += a * b.z;
                acc[r][3] += a * b.w;
            }
        }
        __syncthreads();
    }
#pragma unroll
    for (int r = 0; r < 4; r++) {
        int row = rowBase + ty * 4 + r;
        if (row < Nn) {
            __half2 h01 = __floats2half2_rn(acc[r][0], acc[r][1]);
            __half2 h23 = __floats2half2_rn(acc[r][2], acc[r][3]);
            uint2 u;
            u.x = *(unsigned int*)&h01;
            u.y = *(unsigned int*)&h23;
            *(uint2*)&g_tmp[row * Hh + tx * 4] = u;   // 8B aligned
        }
    }
}

__global__ void gemm_kernel(const float* __restrict__ A, const float* __restrict__ W) {
    gemm_body(A, W, blockIdx.x * GEMM_ROWS);
}

// ---------------- phase 1: degree count fused with GEMM1 (rows 0..5023) ------
__global__ void cnt_gemm1a_kernel(const int* __restrict__ dst,
                                  const float* __restrict__ A,
                                  const float* __restrict__ W) {
    if (blockIdx.x < NB_GEMM_A) {
        gemm_body(A, W, blockIdx.x * GEMM_ROWS);
    } else {
        int e0 = (blockIdx.x - NB_GEMM_A) * EDGE_TPB + threadIdx.x;
        int d[EDGE_BATCH];
#pragma unroll
        for (int j = 0; j < EDGE_BATCH; j++) {
            int e = e0 + j * (NB_EDGE * EDGE_TPB);
            d[j] = (e < Ee) ? dst[e] : -1;
        }
#pragma unroll
        for (int j = 0; j < EDGE_BATCH; j++)
            if (d[j] >= 0) atomicAdd(&g_cnt[d[j]], 1);
    }
}

// ---------------- scan: exclusive prefix of g_cnt; emits dinv & cur ----------
__global__ void scan_kernel() {
    __shared__ int wsum[32];
    __shared__ int carry_s;
    int t = threadIdx.x, lane = t & 31, w = t >> 5;
    if (t == 0) carry_s = 0;
    __syncthreads();
    for (int base = 0; base < Nn; base += 1024) {
        int i = base + t;
        int v = (i < Nn) ? g_cnt[i] : 0;
        int incl = v;
#pragma unroll
        for (int o = 1; o < 32; o <<= 1) {
            int x = __shfl_up_sync(0xffffffffu, incl, o);
            if (lane >= o) incl += x;
        }
        if (lane == 31) wsum[w] = incl;
        __syncthreads();
        if (w == 0) {
            int x = wsum[lane];
            int s2 = x;
#pragma unroll
            for (int o = 1; o < 32; o <<= 1) {
                int y = __shfl_up_sync(0xffffffffu, s2, o);
                if (lane >= o) s2 += y;
            }
            wsum[lane] = s2 - x;   // exclusive warp offsets
        }
        __syncthreads();
        int carry = carry_s;
        if (i < Nn) {
            int off = carry + wsum[w] + incl - v;
            g_off[i] = off;
            g_cur[i] = off;
            g_dinv[i] = rsqrtf((float)v + 1.0f);  // +1 self loop
        }
        __syncthreads();
        if (t == 1023) carry_s = carry + wsum[31] + incl;
        __syncthreads();
    }
    if (threadIdx.x == 0) g_off[Nn] = carry_s;
}

// ---------------- phase 2: CSR fill fused with GEMM1 (rows 5024..9999) -------
__global__ void fill_gemm1b_kernel(const int* __restrict__ src, const int* __restrict__ dst,
                                   const float* __restrict__ A, const float* __restrict__ W) {
    if (blockIdx.x < NB_GEMM_B) {
        gemm_body(A, W, (blockIdx.x + NB_GEMM_A) * GEMM_ROWS);
    } else {
        int e0 = (blockIdx.x - NB_GEMM_B) * EDGE_TPB + threadIdx.x;
        int s[EDGE_BATCH], d[EDGE_BATCH];
        float nm[EDGE_BATCH];
#pragma unroll
        for (int j = 0; j < EDGE_BATCH; j++) {
            int e = e0 + j * (NB_EDGE * EDGE_TPB);
            if (e < Ee) {
                s[j] = src[e];
                d[j] = dst[e];
            } else {
                s[j] = -1;
                d[j] = 0;
            }
        }
#pragma unroll
        for (int j = 0; j < EDGE_BATCH; j++)
            if (s[j] >= 0) nm[j] = g_dinv[s[j]] * g_dinv[d[j]];
        int pos[EDGE_BATCH];
#pragma unroll
        for (int j = 0; j < EDGE_BATCH; j++)
            pos[j] = (s[j] >= 0) ? atomicAdd(&g_cur[d[j]], 1) : -1;
#pragma unroll
        for (int j = 0; j < EDGE_BATCH; j++)
            if (pos[j] >= 0)
                g_edge[pos[j]] = make_int2(s[j] * Hh, __float_as_int(nm[j]));
    }
}

// ---------------- fused gather + epilogue (fp16 messages) --------------------
// one warp per destination node; meta-prefetch software pipeline; no atomics.
// mode: 1 = relu -> g_h, 0 = linear -> g_h, 2 = linear -> pool atomics
__device__ __forceinline__ float4 ld_msg(int off) {
    uint2 u = *(const uint2*)&g_tmp[off];
    __half2 h0 = *(__half2*)&u.x;
    __half2 h1 = *(__half2*)&u.y;
    float2 f0 = __half22float2(h0);
    float2 f1 = __half22float2(h1);
    return make_float4(f0.x, f0.y, f1.x, f1.y);
}

__global__ void gather_kernel(const float* __restrict__ bias, int mode,
                              const int* __restrict__ batch) {
    int t = blockIdx.x * blockDim.x + threadIdx.x;
    int i = t >> 5;          // node
    int lane = t & 31;
    if (i >= Nn) return;

    int beg = g_off[i];
    int end = g_off[i + 1];
    int lo4 = lane * 4;

    float4 acc = make_float4(0.f, 0.f, 0.f, 0.f);
    int n4 = (end - beg) >> 2;   // full 4-edge iterations
    int p = beg;

    int2 m0, m1, m2, m3;
    if (n4 > 0) {
        m0 = g_edge[p + 0];
        m1 = g_edge[p + 1];
        m2 = g_edge[p + 2];
        m3 = g_edge[p + 3];
    }
    for (int it = 0; it < n4; it++) {
        int2 c0 = m0, c1 = m1, c2 = m2, c3 = m3;
        int np = p + 4;
        if (it + 1 < n4) {        // prefetch next metas before dependent msg loads
            m0 = g_edge[np + 0];
            m1 = g_edge[np + 1];
            m2 = g_edge[np + 2];
            m3 = g_edge[np + 3];
        }
        float4 v0 = ld_msg(c0.x + lo4);
        float4 v1 = ld_msg(c1.x + lo4);
        float4 v2 = ld_msg(c2.x + lo4);
        float4 v3 = ld_msg(c3.x + lo4);
        float n0 = __int_as_float(c0.y), n1 = __int_as_float(c1.y);
        float n2 = __int_as_float(c2.y), n3 = __int_as_float(c3.y);
        acc.x += n0 * v0.x + n1 * v1.x + n2 * v2.x + n3 * v3.x;
        acc.y += n0 * v0.y + n1 * v1.y + n2 * v2.y + n3 * v3.y;
        acc.z += n0 * v0.z + n1 * v1.z + n2 * v2.z + n3 * v3.z;
        acc.w += n0 * v0.w + n1 * v1.w + n2 * v2.w + n3 * v3.w;
        p = np;
    }
    for (; p < end; p++) {
        int2 e = g_edge[p];
        float nm = __int_as_float(e.y);
        float4 v = ld_msg(e.x + lo4);
        acc.x += nm * v.x;
        acc.y += nm * v.y;
        acc.z += nm * v.z;
        acc.w += nm * v.w;
    }

    // self-loop + bias
    float di = g_dinv[i];
    float d2 = di * di;
    float4 tv = ld_msg(i * Hh + lo4);
    float4 b = ((const float4*)bias)[lane];
    float4 r;
    r.x = acc.x + d2 * tv.x + b.x;
    r.y = acc.y + d2 * tv.y + b.y;
    r.z = acc.z + d2 * tv.z + b.z;
    r.w = acc.w + d2 * tv.w + b.w;

    if (mode == 1) {
        r.x = fmaxf(r.x, 0.f);
        r.y = fmaxf(r.y, 0.f);
        r.z = fmaxf(r.z, 0.f);
        r.w = fmaxf(r.w, 0.f);
        ((float4*)g_h)[i * 32 + lane] = r;
    } else if (mode == 0) {
        ((float4*)g_h)[i * 32 + lane] = r;
    } else {
        int bg = batch[i];
        float* pp = &g_pool[bg * Hh + lo4];
        atomicAdd(pp + 0, r.x);
        atomicAdd(pp + 1, r.y);
        atomicAdd(pp + 2, r.z);
        atomicAdd(pp + 3, r.w);
        if (lane == 0) atomicAdd(&g_pool[Bb * Hh + bg], 1.0f);
    }
}

// ---------------- head + tail-zero for next replay ---------------------------
__global__ void head_tail_kernel(const float* __restrict__ Wp, const float* __restrict__ bp,
                                 float* __restrict__ out) {
    if (blockIdx.x < 8) {
        int t = blockIdx.x * blockDim.x + threadIdx.x;
        int g = t >> 5;
        int lane = t & 31;
        if (g >= Bb) return;
        float c = g_pool[Bb * Hh + g];
        float inv = 1.0f / fmaxf(c, 1.0f);
        float4 v = ((const float4*)g_pool)[g * 32 + lane];
        float4 w = ((const float4*)Wp)[lane];
        float s = v.x * w.x + v.y * w.y + v.z * w.z + v.w * w.w;
#pragma unroll
        for (int o = 16; o; o >>= 1) s += __shfl_xor_sync(0xffffffffu, s, o);
        if (lane == 0) {
            out[g] = s * inv + bp[0];
            g_pool[Bb * Hh + g] = 0.0f;           // re-zero count for next replay
        }
        ((float4*)g_pool)[g * 32 + lane] = make_float4(0.f, 0.f, 0.f, 0.f);
    } else {
        int i = (blockIdx.x - 8) * blockDim.x + threadIdx.x;
        if (i < Nn) g_cnt[i] = 0;                 // re-zero degrees for next replay
    }
}

// ---------------- launch ----------------------------------------------------
extern "C" void kernel_launch(void* const* d_in, const int* in_sizes, int n_in,
                              void* d_out, int out_size) {
    const float* x     = (const float*)d_in[0];
    const int*   ei    = (const int*)d_in[1];
    const int*   batch = (const int*)d_in[2];
    const float* W1    = (const float*)d_in[3];
    const float* b1    = (const float*)d_in[4];
    const float* W2    = (const float*)d_in[5];
    const float* b2    = (const float*)d_in[6];
    const float* W3    = (const float*)d_in[7];
    const float* b3    = (const float*)d_in[8];
    const float* Wp    = (const float*)d_in[9];
    const float* bp    = (const float*)d_in[10];
    float* out = (float*)d_out;

    const int* src = ei;        // edge_index[0]
    const int* dst = ei + Ee;   // edge_index[1]

    float* hbuf = nullptr;
    cudaGetSymbolAddress((void**)&hbuf, g_h);

    const int T = 256;
    int nb_Nw = (Nn * 32 + T - 1) / T;        // 1250

    // phase 1: degree count || GEMM1 (first half of rows)
    cnt_gemm1a_kernel<<<NB_GEMM_A + NB_EDGE, T>>>(dst, x, W1);
    // offsets + dinv
    scan_kernel<<<1, 1024>>>();
    // phase 2: CSR fill || GEMM1 (second half of rows)
    fill_gemm1b_kernel<<<NB_GEMM_B + NB_EDGE, T>>>(src, dst, x, W1);

    // layer 1 aggregate
    gather_kernel<<<nb_Nw, T>>>(b1, 1, batch);

    // layer 2
    gemm_kernel<<<NB_GEMM, T>>>(hbuf, W2);
    gather_kernel<<<nb_Nw, T>>>(b2, 1, batch);

    // layer 3 (fused with pooling)
    gemm_kernel<<<NB_GEMM, T>>>(hbuf, W3);
    gather_kernel<<<nb_Nw, T>>>(b3, 2, batch);

    // head + tail-zero (pool & cnt reset for next replay)
    head_tail_kernel<<<8 + (Nn + T - 1) / T, T>>>(Wp, bp, out);
}

// round 17
// speedup vs baseline: 1.7177x; 1.0240x over previous
#include <cuda_runtime.h>
#include <cuda_fp16.h>

#define Nn 10000
#define Ee 640000
#define Hh 128
#define Bb 64

#define GEMM_ROWS 32
#define NB_GEMM   ((Nn + GEMM_ROWS - 1) / GEMM_ROWS)   // 313
#define NB_GEMM_A 157                                   // rows [0, 5024)
#define NB_GEMM_B (NB_GEMM - NB_GEMM_A)                 // 156: rows [5024, 10016)
#define EDGE_TPB  256
#define EDGE_BATCH 4
#define NB_EDGE   (Ee / (EDGE_TPB * EDGE_BATCH))        // 625 (exact)

// ---------------- scratch (device globals) ----------------------------------
__device__ int    g_cnt[Nn];          // zeroed by loader (call 1) then by tail
__device__ int    g_off[Nn + 1];
__device__ int    g_cur[Nn];
__device__ int2   g_edge[Ee];         // {src*Hh, norm bits} per CSR slot
__device__ float  g_dinv[Nn];
__device__ __half g_tmp[Nn * Hh];     // h @ W (per layer), fp16 messages
__device__ float  g_h[Nn * Hh];       // layer output (fp32)
__device__ float  g_pool[Bb * Hh + Bb];  // zeroed by loader then by tail

// ---------------- GEMM body: 32x128 tile, fp32 compute, fp16 store ----------
// 256 threads; thread tile 4 rows x 4 cols; BK=32
__device__ __forceinline__ void gemm_body(const float* __restrict__ A,
                                          const float* __restrict__ W,
                                          int rowBase) {
    __shared__ float As[32][32];
    __shared__ float Ws[32][128];

    int tid = threadIdx.x;
    int tx = tid & 31;    // cols tx*4
    int ty = tid >> 5;    // rows ty*4

    float acc[4][4];
#pragma unroll
    for (int r = 0; r < 4; r++)
#pragma unroll
        for (int c = 0; c < 4; c++) acc[r][c] = 0.0f;

    for (int kk = 0; kk < Hh; kk += 32) {
        // A tile: 32 rows x 32 k = 256 float4, 1 per thread
        {
            int r = tid >> 3, c4 = tid & 7;
            int row = rowBase + r;
            float4 v = make_float4(0.f, 0.f, 0.f, 0.f);
            if (row < Nn) v = *(const float4*)&A[row * Hh + kk + c4 * 4];
            *(float4*)&As[r][c4 * 4] = v;
        }
        // W tile: 32 k x 128 cols = 1024 float4, 4 per thread
#pragma unroll
        for (int i = 0; i < 4; i++) {
            int lin = i * 256 + tid;
            int r = lin >> 5, c4 = lin & 31;
            *(float4*)&Ws[r][c4 * 4] = *(const float4*)&W[(kk + r) * Hh + c4 * 4];
        }
        __syncthreads();
#pragma unroll
        for (int k = 0; k < 32; k++) {
            float4 b = *(float4*)&Ws[k][tx * 4];
#pragma unroll
            for (int r = 0; r < 4; r++) {
                float a = As[ty * 4 + r][k];
                acc[r][0] += a * b.x;
                acc[r][1] += a * b.y;
                acc[r][2] += a * b.z;
                acc[r][3] += a * b.w;
            }
        }
        __syncthreads();
    }
#pragma unroll
    for (int r = 0; r < 4; r++) {
        int row = rowBase + ty * 4 + r;
        if (row < Nn) {
            __half2 h01 = __floats2half2_rn(acc[r][0], acc[r][1]);
            __half2 h23 = __floats2half2_rn(acc[r][2], acc[r][3]);
            uint2 u;
            u.x = *(unsigned int*)&h01;
            u.y = *(unsigned int*)&h23;
            *(uint2*)&g_tmp[row * Hh + tx * 4] = u;   // 8B aligned
        }
    }
}

__global__ void gemm_kernel(const float* __restrict__ A, const float* __restrict__ W) {
    gemm_body(A, W, blockIdx.x * GEMM_ROWS);
}

// ---------------- phase 1: degree count fused with GEMM1 (rows 0..5023) ------
__global__ void cnt_gemm1a_kernel(const int* __restrict__ dst,
                                  const float* __restrict__ A,
                                  const float* __restrict__ W) {
    if (blockIdx.x < NB_GEMM_A) {
        gemm_body(A, W, blockIdx.x * GEMM_ROWS);
    } else {
        int e0 = (blockIdx.x - NB_GEMM_A) * EDGE_TPB + threadIdx.x;
        int d[EDGE_BATCH];
#pragma unroll
        for (int j = 0; j < EDGE_BATCH; j++) {
            int e = e0 + j * (NB_EDGE * EDGE_TPB);
            d[j] = (e < Ee) ? dst[e] : -1;
        }
#pragma unroll
        for (int j = 0; j < EDGE_BATCH; j++)
            if (d[j] >= 0) atomicAdd(&g_cnt[d[j]], 1);
    }
}

// ---------------- scan: exclusive prefix of g_cnt; emits dinv & cur ----------
__global__ void scan_kernel() {
    __shared__ int wsum[32];
    __shared__ int carry_s;
    int t = threadIdx.x, lane = t & 31, w = t >> 5;
    if (t == 0) carry_s = 0;
    __syncthreads();
    for (int base = 0; base < Nn; base += 1024) {
        int i = base + t;
        int v = (i < Nn) ? g_cnt[i] : 0;
        int incl = v;
#pragma unroll
        for (int o = 1; o < 32; o <<= 1) {
            int x = __shfl_up_sync(0xffffffffu, incl, o);
            if (lane >= o) incl += x;
        }
        if (lane == 31) wsum[w] = incl;
        __syncthreads();
        if (w == 0) {
            int x = wsum[lane];
            int s2 = x;
#pragma unroll
            for (int o = 1; o < 32; o <<= 1) {
                int y = __shfl_up_sync(0xffffffffu, s2, o);
                if (lane >= o) s2 += y;
            }
            wsum[lane] = s2 - x;   // exclusive warp offsets
        }
        __syncthreads();
        int carry = carry_s;
        if (i < Nn) {
            int off = carry + wsum[w] + incl - v;
            g_off[i] = off;
            g_cur[i] = off;
            g_dinv[i] = rsqrtf((float)v + 1.0f);  // +1 self loop
        }
        __syncthreads();
        if (t == 1023) carry_s = carry + wsum[31] + incl;
        __syncthreads();
    }
    if (threadIdx.x == 0) g_off[Nn] = carry_s;
}

// ---------------- phase 2: CSR fill fused with GEMM1 (rows 5024..9999) -------
__global__ void fill_gemm1b_kernel(const int* __restrict__ src, const int* __restrict__ dst,
                                   const float* __restrict__ A, const float* __restrict__ W) {
    if (blockIdx.x < NB_GEMM_B) {
        gemm_body(A, W, (blockIdx.x + NB_GEMM_A) * GEMM_ROWS);
    } else {
        int e0 = (blockIdx.x - NB_GEMM_B) * EDGE_TPB + threadIdx.x;
        int s[EDGE_BATCH], d[EDGE_BATCH];
        float nm[EDGE_BATCH];
#pragma unroll
        for (int j = 0; j < EDGE_BATCH; j++) {
            int e = e0 + j * (NB_EDGE * EDGE_TPB);
            if (e < Ee) {
                s[j] = src[e];
                d[j] = dst[e];
            } else {
                s[j] = -1;
                d[j] = 0;
            }
        }
#pragma unroll
        for (int j = 0; j < EDGE_BATCH; j++)
            if (s[j] >= 0) nm[j] = g_dinv[s[j]] * g_dinv[d[j]];
        int pos[EDGE_BATCH];
#pragma unroll
        for (int j = 0; j < EDGE_BATCH; j++)
            pos[j] = (s[j] >= 0) ? atomicAdd(&g_cur[d[j]], 1) : -1;
#pragma unroll
        for (int j = 0; j < EDGE_BATCH; j++)
            if (pos[j] >= 0)
                g_edge[pos[j]] = make_int2(s[j] * Hh, __float_as_int(nm[j]));
    }
}

// ---------------- fused gather + epilogue (fp16 messages) --------------------
// TWO warps per destination node (each half of the edge list), merged via smem.
// 256 threads = 8 warps = 4 nodes/block; 2500 blocks cover N=10000 exactly.
// mode: 1 = relu -> g_h, 0 = linear -> g_h, 2 = linear -> pool atomics
__device__ __forceinline__ float4 ld_msg(int off) {
    uint2 u = *(const uint2*)&g_tmp[off];
    __half2 h0 = *(__half2*)&u.x;
    __half2 h1 = *(__half2*)&u.y;
    float2 f0 = __half22float2(h0);
    float2 f1 = __half22float2(h1);
    return make_float4(f0.x, f0.y, f1.x, f1.y);
}

__global__ void gather_kernel(const float* __restrict__ bias, int mode,
                              const int* __restrict__ batch) {
    __shared__ float4 part[4][32];

    int tid = threadIdx.x;
    int w = tid >> 5, lane = tid & 31;
    int nib = w >> 1;              // node index within block (0..3)
    int sub = w & 1;               // which half of the edge list
    int i = blockIdx.x * 4 + nib;  // always < Nn (exact cover)
    int lo4 = lane * 4;

    int beg = g_off[i];
    int end = g_off[i + 1];
    int half = beg + ((end - beg) >> 1);
    int p  = sub ? half : beg;
    int pe = sub ? end : half;

    float4 acc = make_float4(0.f, 0.f, 0.f, 0.f);
    for (; p + 3 < pe; p += 4) {
        int2 e0 = g_edge[p + 0], e1 = g_edge[p + 1], e2 = g_edge[p + 2], e3 = g_edge[p + 3];
        float n0 = __int_as_float(e0.y), n1 = __int_as_float(e1.y);
        float n2 = __int_as_float(e2.y), n3 = __int_as_float(e3.y);
        float4 v0 = ld_msg(e0.x + lo4);
        float4 v1 = ld_msg(e1.x + lo4);
        float4 v2 = ld_msg(e2.x + lo4);
        float4 v3 = ld_msg(e3.x + lo4);
        acc.x += n0 * v0.x + n1 * v1.x + n2 * v2.x + n3 * v3.x;
        acc.y += n0 * v0.y + n1 * v1.y + n2 * v2.y + n3 * v3.y;
        acc.z += n0 * v0.z + n1 * v1.z + n2 * v2.z + n3 * v3.z;
        acc.w += n0 * v0.w + n1 * v1.w + n2 * v2.w + n3 * v3.w;
    }
    for (; p < pe; p++) {
        int2 e = g_edge[p];
        float nm = __int_as_float(e.y);
        float4 v = ld_msg(e.x + lo4);
        acc.x += nm * v.x;
        acc.y += nm * v.y;
        acc.z += nm * v.z;
        acc.w += nm * v.w;
    }

    if (sub == 1) part[nib][lane] = acc;
    __syncthreads();

    if (sub == 0) {
        float4 q = part[nib][lane];
        acc.x += q.x;
        acc.y += q.y;
        acc.z += q.z;
        acc.w += q.w;

        // self-loop + bias
        float di = g_dinv[i];
        float d2 = di * di;
        float4 tv = ld_msg(i * Hh + lo4);
        float4 b = ((const float4*)bias)[lane];
        float4 r;
        r.x = acc.x + d2 * tv.x + b.x;
        r.y = acc.y + d2 * tv.y + b.y;
        r.z = acc.z + d2 * tv.z + b.z;
        r.w = acc.w + d2 * tv.w + b.w;

        if (mode == 1) {
            r.x = fmaxf(r.x, 0.f);
            r.y = fmaxf(r.y, 0.f);
            r.z = fmaxf(r.z, 0.f);
            r.w = fmaxf(r.w, 0.f);
            ((float4*)g_h)[i * 32 + lane] = r;
        } else if (mode == 0) {
            ((float4*)g_h)[i * 32 + lane] = r;
        } else {
            int bg = batch[i];
            float* pp = &g_pool[bg * Hh + lo4];
            atomicAdd(pp + 0, r.x);
            atomicAdd(pp + 1, r.y);
            atomicAdd(pp + 2, r.z);
            atomicAdd(pp + 3, r.w);
            if (lane == 0) atomicAdd(&g_pool[Bb * Hh + bg], 1.0f);
        }
    }
}

// ---------------- head + tail-zero for next replay ---------------------------
__global__ void head_tail_kernel(const float* __restrict__ Wp, const float* __restrict__ bp,
                                 float* __restrict__ out) {
    if (blockIdx.x < 8) {
        int t = blockIdx.x * blockDim.x + threadIdx.x;
        int g = t >> 5;
        int lane = t & 31;
        if (g >= Bb) return;
        float c = g_pool[Bb * Hh + g];
        float inv = 1.0f / fmaxf(c, 1.0f);
        float4 v = ((const float4*)g_pool)[g * 32 + lane];
        float4 w = ((const float4*)Wp)[lane];
        float s = v.x * w.x + v.y * w.y + v.z * w.z + v.w * w.w;
#pragma unroll
        for (int o = 16; o; o >>= 1) s += __shfl_xor_sync(0xffffffffu, s, o);
        if (lane == 0) {
            out[g] = s * inv + bp[0];
            g_pool[Bb * Hh + g] = 0.0f;           // re-zero count for next replay
        }
        ((float4*)g_pool)[g * 32 + lane] = make_float4(0.f, 0.f, 0.f, 0.f);
    } else {
        int i = (blockIdx.x - 8) * blockDim.x + threadIdx.x;
        if (i < Nn) g_cnt[i] = 0;                 // re-zero degrees for next replay
    }
}

// ---------------- launch ----------------------------------------------------
extern "C" void kernel_launch(void* const* d_in, const int* in_sizes, int n_in,
                              void* d_out, int out_size) {
    const float* x     = (const float*)d_in[0];
    const int*   ei    = (const int*)d_in[1];
    const int*   batch = (const int*)d_in[2];
    const float* W1    = (const float*)d_in[3];
    const float* b1    = (const float*)d_in[4];
    const float* W2    = (const float*)d_in[5];
    const float* b2    = (const float*)d_in[6];
    const float* W3    = (const float*)d_in[7];
    const float* b3    = (const float*)d_in[8];
    const float* Wp    = (const float*)d_in[9];
    const float* bp    = (const float*)d_in[10];
    float* out = (float*)d_out;

    const int* src = ei;        // edge_index[0]
    const int* dst = ei + Ee;   // edge_index[1]

    float* hbuf = nullptr;
    cudaGetSymbolAddress((void**)&hbuf, g_h);

    const int T = 256;
    int nb_gather = Nn / 4;     // 2500 blocks, 2 warps per node

    // phase 1: degree count || GEMM1 (first half of rows)
    cnt_gemm1a_kernel<<<NB_GEMM_A + NB_EDGE, T>>>(dst, x, W1);
    // offsets + dinv
    scan_kernel<<<1, 1024>>>();
    // phase 2: CSR fill || GEMM1 (second half of rows)
    fill_gemm1b_kernel<<<NB_GEMM_B + NB_EDGE, T>>>(src, dst, x, W1);

    // layer 1 aggregate
    gather_kernel<<<nb_gather, T>>>(b1, 1, batch);

    // layer 2
    gemm_kernel<<<NB_GEMM, T>>>(hbuf, W2);
    gather_kernel<<<nb_gather, T>>>(b2, 1, batch);

    // layer 3 (fused with pooling)
    gemm_kernel<<<NB_GEMM, T>>>(hbuf, W3);
    gather_kernel<<<nb_gather, T>>>(b3, 2, batch);

    // head + tail-zero (pool & cnt reset for next replay)
    head_tail_kernel<<<8 + (Nn + T - 1) / T, T>>>(Wp, bp, out);
}